// round 16
// baseline (speedup 1.0000x reference)
#include <cuda_runtime.h>
#include <cuda_fp16.h>
#include <cstdint>
#include <math.h>

// Problem constants (Llama-3-8B-like prefill)
#define T_TOK 4096
#define D_MODEL 4096
#define N_Q 32
#define N_KV 8
#define HD 128
#define SEQ 1024
#define BATCH 4
#define NQKV 6144   // N_Q*HD + 2*N_KV*HD

// Scratch (allocation-free rule: __device__ globals), all fp16
__device__ __half g_xh[T_TOK * D_MODEL];
__device__ __half g_wqkvh[D_MODEL * NQKV];      // [D][ wq(4096) | wk(1024) | wv(1024) ]
__device__ __half g_woh[N_Q * HD * D_MODEL];
__device__ __half g_qh[T_TOK * N_Q * HD];
__device__ __half g_kh[T_TOK * N_KV * HD];
__device__ __half g_vh[T_TOK * N_KV * HD];
__device__ __half g_atth[T_TOK * N_Q * HD];

__device__ __forceinline__ uint32_t packh2(float a, float b) {
    __half2 h = __floats2half2_rn(a, b);
    return *(uint32_t*)&h;
}

#define MMA_F16(d, a, b)                                                      \
    asm volatile(                                                             \
        "mma.sync.aligned.m16n8k16.row.col.f32.f16.f16.f32 "                  \
        "{%0,%1,%2,%3}, {%4,%5,%6,%7}, {%8,%9}, {%0,%1,%2,%3};"               \
        : "+f"((d)[0]), "+f"((d)[1]), "+f"((d)[2]), "+f"((d)[3])              \
        : "r"((a)[0]), "r"((a)[1]), "r"((a)[2]), "r"((a)[3]),                 \
          "r"((b)[0]), "r"((b)[1]))

#define CP16(dst, src) \
    asm volatile("cp.async.cg.shared.global [%0], [%1], 16;" :: "r"(dst), "l"(src))
#define CP_COMMIT() asm volatile("cp.async.commit_group;" ::: "memory")

#define LDSM4(r0, r1, r2, r3, addr)                                           \
    asm volatile("ldmatrix.sync.aligned.m8n8.x4.shared.b16 {%0,%1,%2,%3}, [%4];" \
        : "=r"(r0), "=r"(r1), "=r"(r2), "=r"(r3) : "r"(addr))
#define LDSM4T(r0, r1, r2, r3, addr)                                          \
    asm volatile("ldmatrix.sync.aligned.m8n8.x4.trans.shared.b16 {%0,%1,%2,%3}, [%4];" \
        : "=r"(r0), "=r"(r1), "=r"(r2), "=r"(r3) : "r"(addr))

// ---------------------------------------------------------------------------
// fp32 -> fp16 conversion, contiguous, 8 elems/thread
// ---------------------------------------------------------------------------
__global__ void conv_h(const float* __restrict__ in, __half* __restrict__ out, int n8) {
    int i = blockIdx.x * 256 + threadIdx.x;
    if (i < n8) {
        float4 a = ((const float4*)in)[2 * i];
        float4 b = ((const float4*)in)[2 * i + 1];
        ((uint4*)out)[i] = make_uint4(packh2(a.x, a.y), packh2(a.z, a.w),
                                      packh2(b.x, b.y), packh2(b.z, b.w));
    }
}

// ---------------------------------------------------------------------------
// fp32 [R][C] -> fp16 segment of concatenated weights: out row stride OS,
// column offset CO. 8 elems/thread; C multiple of 8.
// ---------------------------------------------------------------------------
__global__ void conv_seg(const float* __restrict__ in, __half* __restrict__ out,
                         int C, int OS, int CO, int n8) {
    int i = blockIdx.x * 256 + threadIdx.x;
    if (i < n8) {
        int e = i * 8;
        int r = e / C, c = e % C;
        float4 a = ((const float4*)in)[2 * i];
        float4 b = ((const float4*)in)[2 * i + 1];
        uint4 o = make_uint4(packh2(a.x, a.y), packh2(a.z, a.w),
                             packh2(b.x, b.y), packh2(b.z, b.w));
        *(uint4*)(out + (size_t)r * OS + CO + c) = o;
    }
}

// ---------------------------------------------------------------------------
// FP16 mma.sync GEMM: C[M,N] = A[M,K] @ W[K,N]. (verified R12/R14)
// 128x128 CTA tile, BK=32, 128 thr, 4 warps (2x2), warp tile 64x64.
// All fragments via ldmatrix (A non-trans; W trans from dense [k][n]).
// 4-stage cp.async, 1 barrier/chunk.
// out_half==1: epilogue routes 128-col tiles to q/k/v by column segment.
// ---------------------------------------------------------------------------
#define AH 40
#define BH 136
#define STGH (128 * AH + 32 * BH)   // 9472 halves
__global__ __launch_bounds__(128, 2) void gemm_h(const __half* __restrict__ A,
                                                 const __half* __restrict__ W,
                                                 void* __restrict__ Cout,
                                                 int Kdim, int Ndim, int out_half) {
    extern __shared__ __half shh[];
    const uint32_t shb = (uint32_t)__cvta_generic_to_shared(shh);
    const int tid = threadIdx.x, lane = tid & 31, w = tid >> 5;
    const int g = lane >> 2, tig = lane & 3;
    const int wm = w & 1, wn = w >> 1;
    const int cm0 = blockIdx.y * 128, cn0 = blockIdx.x * 128;
    const int nchunk = Kdim >> 5;

    const int ti = lane >> 3, ri = lane & 7;
    const uint32_t offA = (uint32_t)((((ti & 1) * 8 + ri) * AH + (ti >> 1) * 8) * 2);
    const uint32_t offB = (uint32_t)((((ti & 1) * 8 + ri) * BH + (ti >> 1) * 8) * 2);

    auto load = [&](int c, int s) {
        const uint32_t sb = shb + s * (STGH * 2);
#pragma unroll
        for (int i = 0; i < 4; i++) {
            int seg = i * 128 + tid;
            int row = seg >> 2, ks = seg & 3;
            CP16(sb + (row * AH + ks * 8) * 2,
                 A + (size_t)(cm0 + row) * Kdim + c * 32 + ks * 8);
        }
        const uint32_t bb = sb + 128 * AH * 2;
#pragma unroll
        for (int i = 0; i < 4; i++) {
            int seg = i * 128 + tid;
            int row = seg >> 4, ns = seg & 15;
            CP16(bb + (row * BH + ns * 8) * 2,
                 W + (size_t)(c * 32 + row) * Ndim + cn0 + ns * 8);
        }
    };

    float acc[4][8][4];
#pragma unroll
    for (int i = 0; i < 4; i++)
#pragma unroll
        for (int j = 0; j < 8; j++)
#pragma unroll
            for (int r = 0; r < 4; r++) acc[i][j][r] = 0.0f;

    load(0, 0); CP_COMMIT();
    load(1, 1); CP_COMMIT();
    load(2, 2); CP_COMMIT();

    for (int c = 0; c < nchunk; c++) {
        asm volatile("cp.async.wait_group 2;" ::: "memory");
        __syncthreads();
        if (c + 3 < nchunk) load(c + 3, (c + 3) & 3);
        CP_COMMIT();

        const uint32_t aBase = shb + (c & 3) * (STGH * 2);
        const uint32_t bBase = aBase + 128 * AH * 2;
#pragma unroll
        for (int h = 0; h < 2; h++) {
            uint32_t afr[4][4], bfr[8][2];
#pragma unroll
            for (int fm = 0; fm < 4; fm++)
                LDSM4(afr[fm][0], afr[fm][1], afr[fm][2], afr[fm][3],
                      aBase + (uint32_t)((((wm * 64 + fm * 16) * AH) + h * 16) * 2) + offA);
#pragma unroll
            for (int p = 0; p < 4; p++)
                LDSM4T(bfr[2 * p][0], bfr[2 * p][1], bfr[2 * p + 1][0], bfr[2 * p + 1][1],
                       bBase + (uint32_t)(((h * 16) * BH + wn * 64 + p * 16) * 2) + offB);
#pragma unroll
            for (int fm = 0; fm < 4; fm++)
#pragma unroll
                for (int fn = 0; fn < 8; fn++)
                    MMA_F16(acc[fm][fn], afr[fm], bfr[fn]);
        }
    }

    const int m0 = cm0 + wm * 64;
    const int n0 = cn0 + wn * 64;
    if (out_half) {
        __half* base;
        int stride, coff;
        if (cn0 < N_Q * HD)                  { base = g_qh; stride = N_Q * HD;  coff = 0; }
        else if (cn0 < N_Q * HD + N_KV * HD) { base = g_kh; stride = N_KV * HD; coff = N_Q * HD; }
        else                                 { base = g_vh; stride = N_KV * HD; coff = N_Q * HD + N_KV * HD; }
#pragma unroll
        for (int fm = 0; fm < 4; fm++) {
            int row = m0 + fm * 16 + g;
#pragma unroll
            for (int fn = 0; fn < 8; fn++) {
                int col = n0 + fn * 8 + tig * 2 - coff;
                *(uint32_t*)(base + (size_t)row * stride + col) =
                    packh2(acc[fm][fn][0], acc[fm][fn][1]);
                *(uint32_t*)(base + (size_t)(row + 8) * stride + col) =
                    packh2(acc[fm][fn][2], acc[fm][fn][3]);
            }
        }
    } else {
        float* Cf = (float*)Cout;
#pragma unroll
        for (int fm = 0; fm < 4; fm++) {
            int row = m0 + fm * 16 + g;
#pragma unroll
            for (int fn = 0; fn < 8; fn++) {
                int col = n0 + fn * 8 + tig * 2;
                float* cp = Cf + (size_t)row * Ndim + col;
                *(float2*)cp = make_float2(acc[fm][fn][0], acc[fm][fn][1]);
                *(float2*)(cp + (size_t)8 * Ndim) = make_float2(acc[fm][fn][2], acc[fm][fn][3]);
            }
        }
    }
}

// ---------------------------------------------------------------------------
// RoPE (NeoX half-split), fp32 math on fp16 data. One block per token.
// ---------------------------------------------------------------------------
__global__ __launch_bounds__(256) void rope_kernel(const int* __restrict__ pos) {
    __shared__ float cs[64], sn[64];
    const int t = blockIdx.x;
    const int tid = threadIdx.x;
    if (tid < 64) {
        float p = (float)pos[t];
        float f = p * __expf(-((float)tid / 64.0f) * 9.210340371976184f);
        cs[tid] = cosf(f);
        sn[tid] = sinf(f);
    }
    __syncthreads();
    __half* qb = g_qh + (size_t)t * N_Q * HD;
    __half* kb = g_kh + (size_t)t * N_KV * HD;
#pragma unroll
    for (int it = tid; it < (N_Q + N_KV) * 64; it += 256) {
        int head = it >> 6, h = it & 63;
        __half* buf = (head < N_Q) ? (qb + head * HD) : (kb + (head - N_Q) * HD);
        float c = cs[h], s = sn[h];
        float x1 = __half2float(buf[h]);
        float x2 = __half2float(buf[h + 64]);
        buf[h] = __float2half_rn(x1 * c - x2 * s);
        buf[h + 64] = __float2half_rn(x2 * c + x1 * s);
    }
}

// ---------------------------------------------------------------------------
// Flash attention (fp16 mma.sync m16n8k16), causal GQA.
// R15: K/V double-buffered via 2-stage cp.async commit-group pipeline —
// tile jt+1 is in flight while tile jt computes. Compute path identical.
// SMEM (halves): Q[128][136], 2x K[64][136], 2x V[64][136], P[128][72].
// ---------------------------------------------------------------------------
#define QH 136
#define KH 136
#define VH 136
#define PH 72
#define KVSTG (64 * KH + 64 * VH)   // halves per KV stage
#define BIG_NEG (-3.0e38f)

__global__ __launch_bounds__(256) void attn_h() {
    extern __shared__ __half smh[];
    __half* Ph = smh + 128 * QH + 2 * KVSTG;
    const uint32_t smb = (uint32_t)__cvta_generic_to_shared(smh);
    const uint32_t QsB = smb;
    const uint32_t Kv0 = smb + 128 * QH * 2;     // stage s at Kv0 + s*KVSTG*2
    const uint32_t PsB = Kv0 + 2 * KVSTG * 2;

    const int mt = blockIdx.x, n = blockIdx.y, b = blockIdx.z;
    const int kvh = n >> 2;
    const int tid = threadIdx.x, lane = tid & 31, w = tid >> 5;
    const int g = lane >> 2, tig = lane & 3;
    const int m0 = mt * 128;
    const int wrow = w * 16;
    const int wr_min = m0 + wrow;

    const int ti = lane >> 3, ri = lane & 7;
    const uint32_t offQ = (uint32_t)((((ti & 1) * 8 + ri) * QH + (ti >> 1) * 8) * 2);
    const uint32_t offK = (uint32_t)((((ti & 1) * 8 + ri) * KH + (ti >> 1) * 8) * 2);
    const uint32_t offV = (uint32_t)((((ti & 1) * 8 + ri) * VH + (ti >> 1) * 8) * 2);
    const uint32_t offP = (uint32_t)((((ti & 1) * 8 + ri) * PH + (ti >> 1) * 8) * 2);

    auto load_kv = [&](int jt, int s) {
        const uint32_t kB = Kv0 + s * (KVSTG * 2);
        const uint32_t vB = kB + 64 * KH * 2;
#pragma unroll
        for (int i = 0; i < 4; i++) {
            int seg = i * 256 + tid;
            int row = seg >> 4, ks = seg & 15;
            size_t gof = ((size_t)(b * SEQ + jt * 64 + row) * N_KV + kvh) * HD + ks * 8;
            CP16(kB + (row * KH + ks * 8) * 2, g_kh + gof);
            CP16(vB + (row * VH + ks * 8) * 2, g_vh + gof);
        }
    };

    // Q tile (group), then prologue KV tile 0 (group)
#pragma unroll
    for (int i = 0; i < 8; i++) {
        int seg = i * 256 + tid;
        int row = seg >> 4, ks = seg & 15;
        CP16(QsB + (row * QH + ks * 8) * 2,
             g_qh + ((size_t)(b * SEQ + m0 + row) * N_Q + n) * HD + ks * 8);
    }
    CP_COMMIT();
    load_kv(0, 0);
    CP_COMMIT();

    float m_i0 = BIG_NEG, m_i1 = BIG_NEG;
    float l_i0 = 0.0f, l_i1 = 0.0f;
    float o[16][4];
#pragma unroll
    for (int fn = 0; fn < 16; fn++)
#pragma unroll
        for (int r = 0; r < 4; r++) o[fn][r] = 0.0f;

    const float scale = 0.08838834764831845f;
    const int ntiles = 2 * (mt + 1);

    for (int jt = 0; jt < ntiles; jt++) {
        __syncthreads();  // stage (jt+1)&1 free: all warps done with tile jt-1
        if (jt + 1 < ntiles) load_kv(jt + 1, (jt + 1) & 1);
        CP_COMMIT();      // commit every iter (possibly empty) -> fixed group count
        asm volatile("cp.async.wait_group 1;" ::: "memory");  // tile jt complete
        __syncthreads();

        const uint32_t KsB = Kv0 + (jt & 1) * (KVSTG * 2);
        const uint32_t VsB = KsB + 64 * KH * 2;

        if (jt * 64 <= wr_min + 15) {
            float s[8][4];
#pragma unroll
            for (int fn = 0; fn < 8; fn++)
#pragma unroll
                for (int r = 0; r < 4; r++) s[fn][r] = 0.0f;

#pragma unroll
            for (int ks = 0; ks < 8; ks++) {
                uint32_t aq[4], bk[8][2];
                LDSM4(aq[0], aq[1], aq[2], aq[3],
                      QsB + (uint32_t)((wrow * QH + ks * 16) * 2) + offQ);
#pragma unroll
                for (int p = 0; p < 4; p++)
                    LDSM4(bk[2 * p][0], bk[2 * p + 1][0], bk[2 * p][1], bk[2 * p + 1][1],
                          KsB + (uint32_t)(((p * 16) * KH + ks * 16) * 2) + offK);
#pragma unroll
                for (int fn = 0; fn < 8; fn++)
                    MMA_F16(s[fn], aq, bk[fn]);
            }

            const int row0 = wr_min + g, row1 = row0 + 8;
            const bool diag = (jt * 64 + 63 > row0);
            float tm0 = BIG_NEG, tm1 = BIG_NEG;
#pragma unroll
            for (int fn = 0; fn < 8; fn++) {
                int colb = jt * 64 + fn * 8 + 2 * tig;
                float v0 = s[fn][0] * scale;
                float v1 = s[fn][1] * scale;
                float v2 = s[fn][2] * scale;
                float v3 = s[fn][3] * scale;
                if (diag) {
                    if (colb > row0) v0 = BIG_NEG;
                    if (colb + 1 > row0) v1 = BIG_NEG;
                    if (colb > row1) v2 = BIG_NEG;
                    if (colb + 1 > row1) v3 = BIG_NEG;
                }
                s[fn][0] = v0; s[fn][1] = v1; s[fn][2] = v2; s[fn][3] = v3;
                tm0 = fmaxf(tm0, fmaxf(v0, v1));
                tm1 = fmaxf(tm1, fmaxf(v2, v3));
            }
            tm0 = fmaxf(tm0, __shfl_xor_sync(0xffffffff, tm0, 1));
            tm0 = fmaxf(tm0, __shfl_xor_sync(0xffffffff, tm0, 2));
            tm1 = fmaxf(tm1, __shfl_xor_sync(0xffffffff, tm1, 1));
            tm1 = fmaxf(tm1, __shfl_xor_sync(0xffffffff, tm1, 2));

            float mn0 = fmaxf(m_i0, tm0), mn1 = fmaxf(m_i1, tm1);
            float corr0 = __expf(m_i0 - mn0), corr1 = __expf(m_i1 - mn1);
            m_i0 = mn0; m_i1 = mn1;

            float ls0 = 0.0f, ls1 = 0.0f;
            __half* pw = Ph + (wrow + g) * PH + 2 * tig;
#pragma unroll
            for (int fn = 0; fn < 8; fn++) {
                float p0 = __expf(s[fn][0] - mn0);
                float p1 = __expf(s[fn][1] - mn0);
                float p2 = __expf(s[fn][2] - mn1);
                float p3 = __expf(s[fn][3] - mn1);
                ls0 += p0 + p1;
                ls1 += p2 + p3;
                *(uint32_t*)(pw + fn * 8) = packh2(p0, p1);
                *(uint32_t*)(pw + 8 * PH + fn * 8) = packh2(p2, p3);
            }
            ls0 += __shfl_xor_sync(0xffffffff, ls0, 1);
            ls0 += __shfl_xor_sync(0xffffffff, ls0, 2);
            ls1 += __shfl_xor_sync(0xffffffff, ls1, 1);
            ls1 += __shfl_xor_sync(0xffffffff, ls1, 2);
            l_i0 = l_i0 * corr0 + ls0;
            l_i1 = l_i1 * corr1 + ls1;

#pragma unroll
            for (int fn = 0; fn < 16; fn++) {
                o[fn][0] *= corr0; o[fn][1] *= corr0;
                o[fn][2] *= corr1; o[fn][3] *= corr1;
            }

            __syncwarp();

#pragma unroll
            for (int ks = 0; ks < 4; ks++) {
                uint32_t ap[4], bv[16][2];
                LDSM4(ap[0], ap[1], ap[2], ap[3],
                      PsB + (uint32_t)((wrow * PH + ks * 16) * 2) + offP);
#pragma unroll
                for (int p = 0; p < 8; p++)
                    LDSM4T(bv[2 * p][0], bv[2 * p][1], bv[2 * p + 1][0], bv[2 * p + 1][1],
                           VsB + (uint32_t)(((ks * 16) * VH + p * 16) * 2) + offV);
#pragma unroll
                for (int fn = 0; fn < 16; fn++)
                    MMA_F16(o[fn], ap, bv[fn]);
            }
            __syncwarp();
        }
    }

    float inv0 = 1.0f / l_i0, inv1 = 1.0f / l_i1;
    __half* op0 = g_atth + ((size_t)(b * SEQ + wr_min + g) * N_Q + n) * HD;
    __half* op1 = op0 + (size_t)8 * N_Q * HD;
#pragma unroll
    for (int fn = 0; fn < 16; fn++) {
        int col = fn * 8 + 2 * tig;
        *(uint32_t*)(op0 + col) = packh2(o[fn][0] * inv0, o[fn][1] * inv0);
        *(uint32_t*)(op1 + col) = packh2(o[fn][2] * inv1, o[fn][3] * inv1);
    }
}

// ---------------------------------------------------------------------------
// Launch
// ---------------------------------------------------------------------------
extern "C" void kernel_launch(void* const* d_in, const int* in_sizes, int n_in,
                              void* d_out, int out_size) {
    const float* x  = (const float*)d_in[0];
    const int* pos  = (const int*)d_in[1];
    const float* Wq = (const float*)d_in[2];
    const float* Wk = (const float*)d_in[3];
    const float* Wv = (const float*)d_in[4];
    const float* Wo = (const float*)d_in[5];
    float* out = (float*)d_out;
    (void)in_sizes; (void)n_in; (void)out_size;

    __half *xh, *wqkvh, *woh, *ath;
    cudaGetSymbolAddress((void**)&xh, g_xh);
    cudaGetSymbolAddress((void**)&wqkvh, g_wqkvh);
    cudaGetSymbolAddress((void**)&woh, g_woh);
    cudaGetSymbolAddress((void**)&ath, g_atth);

    // fp32 -> fp16 conversions (weights concatenated per-row into g_wqkvh)
    conv_h<<<T_TOK * D_MODEL / 2048, 256>>>(x, xh, T_TOK * D_MODEL / 8);
    conv_seg<<<D_MODEL * N_Q * HD / 2048, 256>>>(Wq, wqkvh, N_Q * HD, NQKV, 0,
                                                 D_MODEL * N_Q * HD / 8);
    conv_seg<<<D_MODEL * N_KV * HD / 2048, 256>>>(Wk, wqkvh, N_KV * HD, NQKV, N_Q * HD,
                                                  D_MODEL * N_KV * HD / 8);
    conv_seg<<<D_MODEL * N_KV * HD / 2048, 256>>>(Wv, wqkvh, N_KV * HD, NQKV,
                                                  N_Q * HD + N_KV * HD,
                                                  D_MODEL * N_KV * HD / 8);
    conv_h<<<N_Q * HD * D_MODEL / 2048, 256>>>(Wo, woh, N_Q * HD * D_MODEL / 8);

    const int gemm_smem = 4 * STGH * 2;  // 75776 B
    cudaFuncSetAttribute(gemm_h, cudaFuncAttributeMaxDynamicSharedMemorySize, gemm_smem);

    // Fused QKV projection (one launch, epilogue routes q/k/v)
    gemm_h<<<dim3(NQKV / 128, 32), 128, gemm_smem>>>(xh, wqkvh, nullptr,
                                                     D_MODEL, NQKV, 1);

    // RoPE on fp16 q/k (one block per token)
    rope_kernel<<<T_TOK, 256>>>(pos);

    // Flash attention (fp16 tensor cores, double-buffered KV)
    const int attn_smem = (128 * QH + 2 * KVSTG + 128 * PH) * 2;  // 122880 B
    cudaFuncSetAttribute(attn_h, cudaFuncAttributeMaxDynamicSharedMemorySize, attn_smem);
    attn_h<<<dim3(SEQ / 128, N_Q, BATCH), 256, attn_smem>>>();

    // Output projection (fp32 out)
    gemm_h<<<dim3(32, 32), 128, gemm_smem>>>(ath, woh, out, D_MODEL, D_MODEL, 0);
}